// round 1
// baseline (speedup 1.0000x reference)
#include <cuda_runtime.h>
#include <cuda_bf16.h>
#include <math.h>

// Shapes (fixed by the problem)
#define NQ   10
#define NL   4
#define NDIM 1024      // 2^NQ amplitudes
#define FFN  4096
#define EDIM 1024
#define NTOK 16384     // B*T

// Scratch (allocation-free rule: __device__ globals)
__device__ __align__(16) float g_h[FFN];
__device__ __align__(16) float g_y[EDIM];

__device__ __forceinline__ float2 cmul(float2 a, float2 b) {
    return make_float2(fmaf(a.x, b.x, -a.y * b.y), fmaf(a.x, b.y, a.y * b.x));
}
__device__ __forceinline__ float2 cadd(float2 a, float2 b) {
    return make_float2(a.x + b.x, a.y + b.y);
}

// ---------------------------------------------------------------------------
// Kernel A: 10-qubit statevector sim (1 block, 1024 threads, state in smem)
// then h = relu(W1 @ z + b1) into g_h.
// ---------------------------------------------------------------------------
__global__ void __launch_bounds__(1024, 1)
circuit_h_kernel(const float* __restrict__ params,
                 const float* __restrict__ W1,
                 const float* __restrict__ b1) {
    __shared__ float2 st[NDIM];
    __shared__ float  red[NDIM];
    __shared__ float  zsh[16];

    const int i = threadIdx.x;

    st[i] = make_float2(i == 0 ? 1.0f : 0.0f, 0.0f);
    __syncthreads();

    for (int l = 0; l < NL; l++) {
        // single-qubit fused rotations: U = Rz * Ry * Rx applied on qubit q
        for (int q = 0; q < NQ; q++) {
            const float t0 = params[(l * NQ + q) * 3 + 0];
            const float t1 = params[(l * NQ + q) * 3 + 1];
            const float t2 = params[(l * NQ + q) * 3 + 2];
            float cx, sx, cy, sy, cz, sz;
            sincosf(0.5f * t0, &sx, &cx);
            sincosf(0.5f * t1, &sy, &cy);
            sincosf(0.5f * t2, &sz, &cz);

            // M = Ry*Rx (derived by hand; Rx = [[c,-is],[-is,c]], Ry = [[c,-s],[s,c]])
            const float2 m00 = make_float2( cy * cx,  sy * sx);
            const float2 m01 = make_float2(-sy * cx, -cy * sx);
            const float2 m10 = make_float2( sy * cx, -cy * sx);
            const float2 m11 = make_float2( cy * cx, -sy * sx);
            const float2 ezm = make_float2(cz, -sz);   // e^{-i th/2}
            const float2 ezp = make_float2(cz,  sz);   // e^{+i th/2}
            const float2 u00 = cmul(ezm, m00);
            const float2 u01 = cmul(ezm, m01);
            const float2 u10 = cmul(ezp, m10);
            const float2 u11 = cmul(ezp, m11);

            const int mask = 1 << (NQ - 1 - q);        // qubit q -> bit (9-q)
            const float2 a0 = st[i & ~mask];
            const float2 a1 = st[i |  mask];
            __syncthreads();
            float2 r;
            if (i & mask) r = cadd(cmul(u10, a0), cmul(u11, a1));
            else          r = cadd(cmul(u00, a0), cmul(u01, a1));
            st[i] = r;
            __syncthreads();
        }
        // CNOT ring: (0,1),(1,2),...,(8,9),(9,0)
        for (int e = 0; e < NQ; e++) {
            const int c = (e < NQ - 1) ? e : NQ - 1;
            const int t = (e < NQ - 1) ? e + 1 : 0;
            const int cm = 1 << (NQ - 1 - c);
            const int tm = 1 << (NQ - 1 - t);
            const int src = (i & cm) ? (i ^ tm) : i;
            const float2 tmp = st[src];
            __syncthreads();
            st[i] = tmp;
            __syncthreads();
        }
    }

    // probabilities and <Z_q> = 1 - 2*P(bit q == 1)
    const float2 a = st[i];
    const float p = fmaf(a.x, a.x, a.y * a.y);
    for (int q = 0; q < NQ; q++) {
        const int mask = 1 << (NQ - 1 - q);
        red[i] = (i & mask) ? p : 0.0f;
        __syncthreads();
        #pragma unroll
        for (int s = 512; s > 0; s >>= 1) {
            if (i < s) red[i] += red[i + s];
            __syncthreads();
        }
        if (i == 0) zsh[q] = 1.0f - 2.0f * red[0];
        __syncthreads();
    }

    float z[NQ];
    #pragma unroll
    for (int q = 0; q < NQ; q++) z[q] = zsh[q];

    // h = relu(W1 @ z + b1), W1 is (FFN, NQ) row-major
    for (int j = i; j < FFN; j += 1024) {
        float acc = b1[j];
        #pragma unroll
        for (int q = 0; q < NQ; q++) acc = fmaf(W1[j * NQ + q], z[q], acc);
        g_h[j] = fmaxf(acc, 0.0f);
    }
}

// ---------------------------------------------------------------------------
// Kernel B: y = W2 @ h + b2.  One block per output element e (1024 blocks),
// 256 threads, float4 loads over the contiguous 16KB W2 row.
// ---------------------------------------------------------------------------
__global__ void __launch_bounds__(256)
matvec_kernel(const float* __restrict__ W2, const float* __restrict__ b2) {
    const int e = blockIdx.x;
    const int t = threadIdx.x;
    const float4* __restrict__ w4 = (const float4*)(W2 + (size_t)e * FFN);
    const float4* __restrict__ h4 = (const float4*)g_h;

    float acc = 0.0f;
    #pragma unroll
    for (int j = 0; j < 4; j++) {
        const float4 w = w4[t + 256 * j];
        const float4 h = h4[t + 256 * j];
        acc += w.x * h.x + w.y * h.y + w.z * h.z + w.w * h.w;
    }
    #pragma unroll
    for (int o = 16; o > 0; o >>= 1) acc += __shfl_down_sync(0xffffffffu, acc, o);

    __shared__ float ws[8];
    if ((t & 31) == 0) ws[t >> 5] = acc;
    __syncthreads();
    if (t < 8) {
        float v = ws[t];
        #pragma unroll
        for (int o = 4; o > 0; o >>= 1) v += __shfl_down_sync(0xffu, v, o);
        if (t == 0) g_y[e] = v + b2[e];
    }
}

// ---------------------------------------------------------------------------
// Kernel C: broadcast fill — every token row gets y_row. 64MB store, float4.
// Each block writes 4 rows; col = threadIdx.x selects one float4 of the row.
// ---------------------------------------------------------------------------
__global__ void __launch_bounds__(256)
fill_kernel(float4* __restrict__ out) {
    const int col = threadIdx.x;                 // 0..255 -> float4 within row
    const float4 v = ((const float4*)g_y)[col];
    const size_t base = (size_t)blockIdx.x * 4;  // 4 rows per block
    #pragma unroll
    for (int r = 0; r < 4; r++) {
        out[(base + r) * (EDIM / 4) + col] = v;
    }
}

// ---------------------------------------------------------------------------
// inputs (metadata order): 0=x, 1=W_in, 2=b_in, 3=params, 4=W1, 5=b1, 6=W2, 7=b2
// x / W_in / b_in are dead in the reference (circuit ignores its x argument).
// ---------------------------------------------------------------------------
extern "C" void kernel_launch(void* const* d_in, const int* in_sizes, int n_in,
                              void* d_out, int out_size) {
    const float* params = (const float*)d_in[3];
    const float* W1     = (const float*)d_in[4];
    const float* b1     = (const float*)d_in[5];
    const float* W2     = (const float*)d_in[6];
    const float* b2     = (const float*)d_in[7];
    float* out = (float*)d_out;

    circuit_h_kernel<<<1, 1024>>>(params, W1, b1);
    matvec_kernel<<<EDIM, 256>>>(W2, b2);
    fill_kernel<<<NTOK / 4, 256>>>((float4*)out);
}

// round 2
// speedup vs baseline: 2.1264x; 2.1264x over previous
#include <cuda_runtime.h>
#include <cuda_bf16.h>
#include <math.h>

// Shapes (fixed by the problem)
#define NQ   10
#define NL   4
#define NG   (NL * NQ)   // 40 single-qubit gates
#define NDIM 1024        // 2^NQ amplitudes
#define FFN  4096
#define EDIM 1024
#define NTOK 16384       // B*T

// Scratch (allocation-free rule: __device__ globals)
__device__ __align__(16) float g_h[FFN];
__device__ __align__(16) float g_y[EDIM];

__device__ __forceinline__ float2 cmul(float2 a, float2 b) {
    return make_float2(fmaf(a.x, b.x, -a.y * b.y), fmaf(a.x, b.y, a.y * b.x));
}
__device__ __forceinline__ float2 cfma2(float2 u, float2 a, float2 v, float2 b) {
    // u*a + v*b (complex)
    float re = fmaf(u.x, a.x, -u.y * a.y);
    re = fmaf(v.x, b.x, re);
    re = fmaf(-v.y, b.y, re);
    float im = fmaf(u.x, a.y, u.y * a.x);
    im = fmaf(v.x, b.y, im);
    im = fmaf(v.y, b.x, im);
    return make_float2(re, im);
}

// ---------------------------------------------------------------------------
// Kernel A: 10-qubit statevector sim (1 block, 1024 threads).
//   phase 1: threads 0..39 build all 40 fused gate matrices in parallel
//   phase 2: gate loop, double-buffered state, 1 barrier per gate
//   phase 3: per-layer CNOT ring collapsed to ONE permutation step
//   phase 4: <Z_q> via warp shuffles (1 barrier)
//   phase 5: h = relu(W1 @ z + b1) with float4 loads/stores
// ---------------------------------------------------------------------------
__global__ void __launch_bounds__(1024, 1)
circuit_h_kernel(const float* __restrict__ params,
                 const float* __restrict__ W1,
                 const float* __restrict__ b1) {
    __shared__ float2 U[NG][4];        // u00,u01,u10,u11 per gate
    __shared__ float2 st[2][NDIM];     // double-buffered statevector
    __shared__ float  wsum[32][NQ];    // per-warp partial sums
    __shared__ float  zsh[16];

    const int i    = threadIdx.x;
    const int lane = i & 31;
    const int warp = i >> 5;

    // ---- phase 1: build all gate matrices in parallel -------------------
    if (i < NG) {
        const float t0 = params[i * 3 + 0];
        const float t1 = params[i * 3 + 1];
        const float t2 = params[i * 3 + 2];
        float cx, sx, cy, sy, cz, sz;
        sincosf(0.5f * t0, &sx, &cx);
        sincosf(0.5f * t1, &sy, &cy);
        sincosf(0.5f * t2, &sz, &cz);
        // M = Ry*Rx ; U = Rz*M
        const float2 m00 = make_float2( cy * cx,  sy * sx);
        const float2 m01 = make_float2(-sy * cx, -cy * sx);
        const float2 m10 = make_float2( sy * cx, -cy * sx);
        const float2 m11 = make_float2( cy * cx, -sy * sx);
        const float2 ezm = make_float2(cz, -sz);
        const float2 ezp = make_float2(cz,  sz);
        U[i][0] = cmul(ezm, m00);
        U[i][1] = cmul(ezm, m01);
        U[i][2] = cmul(ezp, m10);
        U[i][3] = cmul(ezp, m11);
    }

    // init state |0...0>
    st[0][i] = make_float2(i == 0 ? 1.0f : 0.0f, 0.0f);

    // ---- compose the CNOT-ring permutation (same every layer) -----------
    // program order: CNOT(0,1),(1,2),...,(8,9),(9,0).  state_new[i]=state_old[src]
    int src = i;
    #pragma unroll
    for (int e = NQ - 1; e >= 0; e--) {
        const int c = (e < NQ - 1) ? e : NQ - 1;
        const int t = (e < NQ - 1) ? e + 1 : 0;
        const int cm = 1 << (NQ - 1 - c);
        const int tm = 1 << (NQ - 1 - t);
        src ^= (src & cm) ? tm : 0;
    }

    __syncthreads();

    // ---- phase 2/3: gate loop ------------------------------------------
    int cur = 0;
    #pragma unroll 1
    for (int l = 0; l < NL; l++) {
        #pragma unroll
        for (int q = 0; q < NQ; q++) {
            const int g = l * NQ + q;
            const float2 u00 = U[g][0], u01 = U[g][1];
            const float2 u10 = U[g][2], u11 = U[g][3];
            const int mask = 1 << (NQ - 1 - q);
            const float2 a0 = st[cur][i & ~mask];
            const float2 a1 = st[cur][i |  mask];
            float2 r;
            if (i & mask) r = cfma2(u10, a0, u11, a1);
            else          r = cfma2(u00, a0, u01, a1);
            st[cur ^ 1][i] = r;
            __syncthreads();
            cur ^= 1;
        }
        // whole CNOT ring as one permutation
        const float2 t = st[cur][src];
        st[cur ^ 1][i] = t;
        __syncthreads();
        cur ^= 1;
    }

    // ---- phase 4: <Z_q> via warp shuffles ------------------------------
    const float2 a = st[cur][i];
    const float p = fmaf(a.x, a.x, a.y * a.y);
    #pragma unroll
    for (int q = 0; q < NQ; q++) {
        const int mask = 1 << (NQ - 1 - q);
        float v = (i & mask) ? p : 0.0f;
        #pragma unroll
        for (int o = 16; o > 0; o >>= 1) v += __shfl_xor_sync(0xffffffffu, v, o);
        if (lane == 0) wsum[warp][q] = v;
    }
    __syncthreads();
    if (i < NQ) {
        float s = 0.0f;
        #pragma unroll
        for (int w = 0; w < 32; w++) s += wsum[w][i];
        zsh[i] = 1.0f - 2.0f * s;
    }
    __syncthreads();

    float z[NQ];
    #pragma unroll
    for (int q = 0; q < NQ; q++) z[q] = zsh[q];

    // ---- phase 5: h = relu(W1 @ z + b1), thread i -> rows 4i..4i+3 ------
    // 4 rows = 40 consecutive floats = 10 aligned float4's starting at 40*i.
    {
        const float4* __restrict__ Wv = ((const float4*)W1) + (size_t)i * 10;
        float f[20];
        float acc[4];

        float4 v0 = Wv[0], v1 = Wv[1], v2 = Wv[2], v3 = Wv[3], v4 = Wv[4];
        f[0]=v0.x; f[1]=v0.y; f[2]=v0.z; f[3]=v0.w;
        f[4]=v1.x; f[5]=v1.y; f[6]=v1.z; f[7]=v1.w;
        f[8]=v2.x; f[9]=v2.y; f[10]=v2.z; f[11]=v2.w;
        f[12]=v3.x; f[13]=v3.y; f[14]=v3.z; f[15]=v3.w;
        f[16]=v4.x; f[17]=v4.y; f[18]=v4.z; f[19]=v4.w;
        acc[0] = 0.0f; acc[1] = 0.0f;
        #pragma unroll
        for (int q = 0; q < NQ; q++) acc[0] = fmaf(f[q],      z[q], acc[0]);
        #pragma unroll
        for (int q = 0; q < NQ; q++) acc[1] = fmaf(f[10 + q], z[q], acc[1]);

        v0 = Wv[5]; v1 = Wv[6]; v2 = Wv[7]; v3 = Wv[8]; v4 = Wv[9];
        f[0]=v0.x; f[1]=v0.y; f[2]=v0.z; f[3]=v0.w;
        f[4]=v1.x; f[5]=v1.y; f[6]=v1.z; f[7]=v1.w;
        f[8]=v2.x; f[9]=v2.y; f[10]=v2.z; f[11]=v2.w;
        f[12]=v3.x; f[13]=v3.y; f[14]=v3.z; f[15]=v3.w;
        f[16]=v4.x; f[17]=v4.y; f[18]=v4.z; f[19]=v4.w;
        acc[2] = 0.0f; acc[3] = 0.0f;
        #pragma unroll
        for (int q = 0; q < NQ; q++) acc[2] = fmaf(f[q],      z[q], acc[2]);
        #pragma unroll
        for (int q = 0; q < NQ; q++) acc[3] = fmaf(f[10 + q], z[q], acc[3]);

        const float4 bb = ((const float4*)b1)[i];
        float4 hv;
        hv.x = fmaxf(acc[0] + bb.x, 0.0f);
        hv.y = fmaxf(acc[1] + bb.y, 0.0f);
        hv.z = fmaxf(acc[2] + bb.z, 0.0f);
        hv.w = fmaxf(acc[3] + bb.w, 0.0f);
        ((float4*)g_h)[i] = hv;
    }
}

// ---------------------------------------------------------------------------
// Kernel B: y = W2 @ h + b2.  One block per output element e (1024 blocks).
// ---------------------------------------------------------------------------
__global__ void __launch_bounds__(256)
matvec_kernel(const float* __restrict__ W2, const float* __restrict__ b2) {
    const int e = blockIdx.x;
    const int t = threadIdx.x;
    const float4* __restrict__ w4 = (const float4*)(W2 + (size_t)e * FFN);
    const float4* __restrict__ h4 = (const float4*)g_h;

    float acc = 0.0f;
    #pragma unroll
    for (int j = 0; j < 4; j++) {
        const float4 w = w4[t + 256 * j];
        const float4 h = h4[t + 256 * j];
        acc += w.x * h.x + w.y * h.y + w.z * h.z + w.w * h.w;
    }
    #pragma unroll
    for (int o = 16; o > 0; o >>= 1) acc += __shfl_down_sync(0xffffffffu, acc, o);

    __shared__ float ws[8];
    if ((t & 31) == 0) ws[t >> 5] = acc;
    __syncthreads();
    if (t < 8) {
        float v = ws[t];
        #pragma unroll
        for (int o = 4; o > 0; o >>= 1) v += __shfl_down_sync(0xffu, v, o);
        if (t == 0) g_y[e] = v + b2[e];
    }
}

// ---------------------------------------------------------------------------
// Kernel C: broadcast fill — 64MB of float4 stores (the HBM floor).
// ---------------------------------------------------------------------------
__global__ void __launch_bounds__(256)
fill_kernel(float4* __restrict__ out) {
    const int col = threadIdx.x;                 // float4 within row
    const float4 v = ((const float4*)g_y)[col];
    const size_t base = (size_t)blockIdx.x * 4;  // 4 rows per block
    #pragma unroll
    for (int r = 0; r < 4; r++) {
        out[(base + r) * (EDIM / 4) + col] = v;
    }
}

// ---------------------------------------------------------------------------
// inputs: 0=x, 1=W_in, 2=b_in, 3=params, 4=W1, 5=b1, 6=W2, 7=b2
// x / W_in / b_in are dead in the reference.
// ---------------------------------------------------------------------------
extern "C" void kernel_launch(void* const* d_in, const int* in_sizes, int n_in,
                              void* d_out, int out_size) {
    const float* params = (const float*)d_in[3];
    const float* W1     = (const float*)d_in[4];
    const float* b1     = (const float*)d_in[5];
    const float* W2     = (const float*)d_in[6];
    const float* b2     = (const float*)d_in[7];
    float* out = (float*)d_out;

    circuit_h_kernel<<<1, 1024>>>(params, W1, b1);
    matvec_kernel<<<EDIM, 256>>>(W2, b2);
    fill_kernel<<<NTOK / 4, 256>>>((float4*)out);
}

// round 3
// speedup vs baseline: 2.2845x; 1.0744x over previous
#include <cuda_runtime.h>
#include <cuda_bf16.h>
#include <math.h>

// Shapes (fixed by the problem)
#define NQ   10
#define NL   4
#define NG   (NL * NQ)   // 40 single-qubit gates
#define NDIM 1024        // 2^NQ amplitudes
#define FFN  4096
#define EDIM 1024
#define NTOK 16384       // B*T

// Scratch (allocation-free rule: __device__ globals)
__device__ __align__(16) float g_h[FFN];
__device__ __align__(16) float g_y[EDIM];

__device__ __forceinline__ float2 cmul(float2 a, float2 b) {
    return make_float2(fmaf(a.x, b.x, -a.y * b.y), fmaf(a.x, b.y, a.y * b.x));
}
__device__ __forceinline__ float2 cfma2(float2 u, float2 a, float2 v, float2 b) {
    // u*a + v*b (complex)
    float re = fmaf(u.x, a.x, -u.y * a.y);
    re = fmaf(v.x, b.x, re);
    re = fmaf(-v.y, b.y, re);
    float im = fmaf(u.x, a.y, u.y * a.x);
    im = fmaf(v.x, b.y, im);
    im = fmaf(v.y, b.x, im);
    return make_float2(re, im);
}

// padded smem index: 1 extra float2 per 32 to kill transpose bank conflicts
#define SIDX(i) ((i) + ((i) >> 5))

// ---------------------------------------------------------------------------
// Kernel A: 10-qubit statevector sim, register-resident amplitude per thread.
// Gates on lane bits via shfl_xor (no smem, no barriers). Layer structure:
//   gates q5..9 (lane-local) -> transpose (1 bar) -> gates q0..4 (lane-local)
//   -> CNOT-ring perm fused with transpose-back (1 bar).
// Then <Z_q> via warp shuffles and h = relu(W1 z + b1).
// ---------------------------------------------------------------------------
__global__ void __launch_bounds__(1024, 1)
circuit_h_kernel(const float* __restrict__ params,
                 const float* __restrict__ W1,
                 const float* __restrict__ b1) {
    __shared__ float2 U[NG][2];             // u00, u01 (u10/u11 derived by conj)
    __shared__ float2 st[2][NDIM + 32];     // padded, double-buffered
    __shared__ float  wsum[32][NQ];
    __shared__ float  zsh[16];

    const int t    = threadIdx.x;
    const int lane = t & 31;
    const int warp = t >> 5;

    // ---- build gate coefficients (threads 0..39) ------------------------
    if (t < NG) {
        const float t0 = params[t * 3 + 0];
        const float t1 = params[t * 3 + 1];
        const float t2 = params[t * 3 + 2];
        float cx, sx, cy, sy, cz, sz;
        sincosf(0.5f * t0, &sx, &cx);
        sincosf(0.5f * t1, &sy, &cy);
        sincosf(0.5f * t2, &sz, &cz);
        // M = Ry*Rx ; U = Rz*M ; u11 = conj(u00), u10 = -conj(u01)
        const float2 m00 = make_float2( cy * cx,  sy * sx);
        const float2 m01 = make_float2(-sy * cx, -cy * sx);
        const float2 ezm = make_float2(cz, -sz);
        U[t][0] = cmul(ezm, m00);
        U[t][1] = cmul(ezm, m01);
    }

    // ---- per-thread precompute ------------------------------------------
    // transpose permutation (self-inverse): swap index bits [9:5] <-> [4:0]
    const int Pt = ((t & 31) << 5) | (t >> 5);
    // CNOT ring gather: s_new[i] = s_old[C(i)], ring (0,1)..(8,9),(9,0)
    int Ct = t;
    #pragma unroll
    for (int e = NQ - 1; e >= 0; e--) {
        const int c = (e < NQ - 1) ? e : NQ - 1;
        const int tq = (e < NQ - 1) ? e + 1 : 0;
        const int cm = 1 << (NQ - 1 - c);
        const int tm = 1 << (NQ - 1 - tq);
        Ct ^= (Ct & cm) ? tm : 0;
    }
    // per-gate-slot sign: slot k uses lane bit (4-k); same for both layouts
    float sgn[5];
    #pragma unroll
    for (int k = 0; k < 5; k++) sgn[k] = (t & (16 >> k)) ? -1.0f : 1.0f;

    // initial state |0..0> in registers
    float2 a = make_float2(t == 0 ? 1.0f : 0.0f, 0.0f);

    __syncthreads();   // U ready

    // ---- gate loop ------------------------------------------------------
    int cur = 0;
    #pragma unroll 1
    for (int l = 0; l < NL; l++) {
        // layout A: qubits 5..9 live on lane bits 4..0
        #pragma unroll
        for (int k = 0; k < 5; k++) {
            const int g = l * NQ + 5 + k;
            float2 u0 = U[g][0];
            float2 u1 = U[g][1];
            const float s = sgn[k];
            u0.y *= s; u1.x *= s;     // bit=1 -> conj(u00), -conj(u01)
            const int m = 16 >> k;
            float2 b;
            b.x = __shfl_xor_sync(0xffffffffu, a.x, m);
            b.y = __shfl_xor_sync(0xffffffffu, a.y, m);
            a = cfma2(u0, a, u1, b);
        }
        // transpose A -> B (thread u now holds s[P(u)])
        st[cur][SIDX(t)] = a;
        __syncthreads();
        a = st[cur][SIDX(Pt)];
        cur ^= 1;
        // layout B: qubits 0..4 live on lane bits 4..0
        #pragma unroll
        for (int k = 0; k < 5; k++) {
            const int g = l * NQ + k;
            float2 u0 = U[g][0];
            float2 u1 = U[g][1];
            const float s = sgn[k];
            u0.y *= s; u1.x *= s;
            const int m = 16 >> k;
            float2 b;
            b.x = __shfl_xor_sync(0xffffffffu, a.x, m);
            b.y = __shfl_xor_sync(0xffffffffu, a.y, m);
            a = cfma2(u0, a, u1, b);
        }
        // CNOT ring + transpose back to layout A in one gather:
        // write to natural order (undo transpose), then gather C(t)
        st[cur][SIDX(Pt)] = a;
        __syncthreads();
        a = st[cur][SIDX(Ct)];
        cur ^= 1;
    }

    // ---- <Z_q> ----------------------------------------------------------
    const float p = fmaf(a.x, a.x, a.y * a.y);
    #pragma unroll
    for (int q = 0; q < NQ; q++) {
        const int mask = 1 << (NQ - 1 - q);
        float v = (t & mask) ? p : 0.0f;
        #pragma unroll
        for (int o = 16; o > 0; o >>= 1) v += __shfl_xor_sync(0xffffffffu, v, o);
        if (lane == 0) wsum[warp][q] = v;
    }
    __syncthreads();
    if (t < NQ) {
        float s = 0.0f;
        #pragma unroll
        for (int w = 0; w < 32; w++) s += wsum[w][t];
        zsh[t] = 1.0f - 2.0f * s;
    }
    __syncthreads();

    float z[NQ];
    #pragma unroll
    for (int q = 0; q < NQ; q++) z[q] = zsh[q];

    // ---- h = relu(W1 @ z + b1); thread t -> rows 4t..4t+3 ---------------
    {
        const float4* __restrict__ Wv = ((const float4*)W1) + (size_t)t * 10;
        float f[20];
        float acc[4];

        float4 v0 = Wv[0], v1 = Wv[1], v2 = Wv[2], v3 = Wv[3], v4 = Wv[4];
        f[0]=v0.x; f[1]=v0.y; f[2]=v0.z; f[3]=v0.w;
        f[4]=v1.x; f[5]=v1.y; f[6]=v1.z; f[7]=v1.w;
        f[8]=v2.x; f[9]=v2.y; f[10]=v2.z; f[11]=v2.w;
        f[12]=v3.x; f[13]=v3.y; f[14]=v3.z; f[15]=v3.w;
        f[16]=v4.x; f[17]=v4.y; f[18]=v4.z; f[19]=v4.w;
        acc[0] = 0.0f; acc[1] = 0.0f;
        #pragma unroll
        for (int q = 0; q < NQ; q++) acc[0] = fmaf(f[q],      z[q], acc[0]);
        #pragma unroll
        for (int q = 0; q < NQ; q++) acc[1] = fmaf(f[10 + q], z[q], acc[1]);

        v0 = Wv[5]; v1 = Wv[6]; v2 = Wv[7]; v3 = Wv[8]; v4 = Wv[9];
        f[0]=v0.x; f[1]=v0.y; f[2]=v0.z; f[3]=v0.w;
        f[4]=v1.x; f[5]=v1.y; f[6]=v1.z; f[7]=v1.w;
        f[8]=v2.x; f[9]=v2.y; f[10]=v2.z; f[11]=v2.w;
        f[12]=v3.x; f[13]=v3.y; f[14]=v3.z; f[15]=v3.w;
        f[16]=v4.x; f[17]=v4.y; f[18]=v4.z; f[19]=v4.w;
        acc[2] = 0.0f; acc[3] = 0.0f;
        #pragma unroll
        for (int q = 0; q < NQ; q++) acc[2] = fmaf(f[q],      z[q], acc[2]);
        #pragma unroll
        for (int q = 0; q < NQ; q++) acc[3] = fmaf(f[10 + q], z[q], acc[3]);

        const float4 bb = ((const float4*)b1)[t];
        float4 hv;
        hv.x = fmaxf(acc[0] + bb.x, 0.0f);
        hv.y = fmaxf(acc[1] + bb.y, 0.0f);
        hv.z = fmaxf(acc[2] + bb.z, 0.0f);
        hv.w = fmaxf(acc[3] + bb.w, 0.0f);
        ((float4*)g_h)[t] = hv;
    }
}

// ---------------------------------------------------------------------------
// Kernel B: y = W2 @ h + b2.  One block per output element (1024 blocks).
// ---------------------------------------------------------------------------
__global__ void __launch_bounds__(256)
matvec_kernel(const float* __restrict__ W2, const float* __restrict__ b2) {
    const int e = blockIdx.x;
    const int t = threadIdx.x;
    const float4* __restrict__ w4 = (const float4*)(W2 + (size_t)e * FFN);
    const float4* __restrict__ h4 = (const float4*)g_h;

    float acc = 0.0f;
    #pragma unroll
    for (int j = 0; j < 4; j++) {
        const float4 w = w4[t + 256 * j];
        const float4 h = h4[t + 256 * j];
        acc += w.x * h.x + w.y * h.y + w.z * h.z + w.w * h.w;
    }
    #pragma unroll
    for (int o = 16; o > 0; o >>= 1) acc += __shfl_down_sync(0xffffffffu, acc, o);

    __shared__ float ws[8];
    if ((t & 31) == 0) ws[t >> 5] = acc;
    __syncthreads();
    if (t < 8) {
        float v = ws[t];
        #pragma unroll
        for (int o = 4; o > 0; o >>= 1) v += __shfl_down_sync(0xffu, v, o);
        if (t == 0) g_y[e] = v + b2[e];
    }
}

// ---------------------------------------------------------------------------
// Kernel C: broadcast fill — 64MB of float4 stores (the HBM floor).
// ---------------------------------------------------------------------------
__global__ void __launch_bounds__(256)
fill_kernel(float4* __restrict__ out) {
    const int col = threadIdx.x;                 // float4 within row
    const float4 v = ((const float4*)g_y)[col];
    const size_t base = (size_t)blockIdx.x * 4;  // 4 rows per block
    #pragma unroll
    for (int r = 0; r < 4; r++) {
        out[(base + r) * (EDIM / 4) + col] = v;
    }
}

// ---------------------------------------------------------------------------
// inputs: 0=x, 1=W_in, 2=b_in, 3=params, 4=W1, 5=b1, 6=W2, 7=b2
// x / W_in / b_in are dead in the reference.
// ---------------------------------------------------------------------------
extern "C" void kernel_launch(void* const* d_in, const int* in_sizes, int n_in,
                              void* d_out, int out_size) {
    const float* params = (const float*)d_in[3];
    const float* W1     = (const float*)d_in[4];
    const float* b1     = (const float*)d_in[5];
    const float* W2     = (const float*)d_in[6];
    const float* b2     = (const float*)d_in[7];
    float* out = (float*)d_out;

    circuit_h_kernel<<<1, 1024>>>(params, W1, b1);
    matvec_kernel<<<EDIM, 256>>>(W2, b2);
    fill_kernel<<<NTOK / 4, 256>>>((float4*)out);
}